// round 3
// baseline (speedup 1.0000x reference)
#include <cuda_runtime.h>
#include <cstddef>

#define NN 8192
#define FF 256
#define MAXNN 1024   // per-row neighbor cap (expected ~83, binomial tail makes >1024 impossible)

__device__ float g_hprime[(size_t)NN * FF];
__device__ float g_fdst[NN];

// ---------------------------------------------------------------------------
// Kernel 1: h_prime = node_feats @ w   (8192x256 @ 256x256, fp32)
// 128x128 tile, 256 threads, 8x8 microtile, K-chunks of 16.
// ---------------------------------------------------------------------------
__global__ __launch_bounds__(256) void gemm_kernel(const float* __restrict__ A,
                                                   const float* __restrict__ W) {
    __shared__ float As[16][128];
    __shared__ float Bs[16][128];

    const int m0 = blockIdx.y * 128;
    const int n0 = blockIdx.x * 128;
    const int tid = threadIdx.x;
    const int tr = tid >> 4;        // 0..15
    const int tc = tid & 15;        // 0..15

    const int ar = tid >> 1;        // 0..127  (A tile row)
    const int ac = (tid & 1) * 8;   // 0 or 8  (A tile col)
    const int br = tid >> 4;        // 0..15   (B tile row)
    const int bc = (tid & 15) * 8;  // 0..120  (B tile col)

    float acc[8][8];
#pragma unroll
    for (int i = 0; i < 8; i++)
#pragma unroll
        for (int j = 0; j < 8; j++) acc[i][j] = 0.f;

    for (int k0 = 0; k0 < 256; k0 += 16) {
        float4 a0 = *(const float4*)&A[(size_t)(m0 + ar) * 256 + k0 + ac];
        float4 a1 = *(const float4*)&A[(size_t)(m0 + ar) * 256 + k0 + ac + 4];
        float4 b0 = *(const float4*)&W[(size_t)(k0 + br) * 256 + n0 + bc];
        float4 b1 = *(const float4*)&W[(size_t)(k0 + br) * 256 + n0 + bc + 4];

        __syncthreads();  // previous iteration's compute done before overwrite
        As[ac + 0][ar] = a0.x; As[ac + 1][ar] = a0.y;
        As[ac + 2][ar] = a0.z; As[ac + 3][ar] = a0.w;
        As[ac + 4][ar] = a1.x; As[ac + 5][ar] = a1.y;
        As[ac + 6][ar] = a1.z; As[ac + 7][ar] = a1.w;
        *(float4*)&Bs[br][bc]     = b0;
        *(float4*)&Bs[br][bc + 4] = b1;
        __syncthreads();

#pragma unroll
        for (int k = 0; k < 16; k++) {
            float4 x0 = *(const float4*)&As[k][tr * 8];
            float4 x1 = *(const float4*)&As[k][tr * 8 + 4];
            float4 y0 = *(const float4*)&Bs[k][tc * 8];
            float4 y1 = *(const float4*)&Bs[k][tc * 8 + 4];
            float ra[8] = {x0.x, x0.y, x0.z, x0.w, x1.x, x1.y, x1.z, x1.w};
            float rb[8] = {y0.x, y0.y, y0.z, y0.w, y1.x, y1.y, y1.z, y1.w};
#pragma unroll
            for (int i = 0; i < 8; i++)
#pragma unroll
                for (int j = 0; j < 8; j++) acc[i][j] += ra[i] * rb[j];
        }
    }

#pragma unroll
    for (int i = 0; i < 8; i++) {
        float* dst = &g_hprime[(size_t)(m0 + tr * 8 + i) * 256 + n0 + tc * 8];
        *(float4*)&dst[0] = make_float4(acc[i][0], acc[i][1], acc[i][2], acc[i][3]);
        *(float4*)&dst[4] = make_float4(acc[i][4], acc[i][5], acc[i][6], acc[i][7]);
    }
}

// ---------------------------------------------------------------------------
// Kernel 2: f_dst[j] = h_prime[j,:] . (w_a @ a[2:4])
// (f_src cancels in the row softmax: softmax(f_src[i]+f_dst[j]) over j ==
//  softmax(f_dst[j]); masked entries underflow to exactly 0 in fp32.)
// 256 threads = 8 warps, one row per warp.
// ---------------------------------------------------------------------------
__global__ __launch_bounds__(256) void fdst_kernel(const float* __restrict__ w_a,
                                                   const float* __restrict__ a) {
    __shared__ float va[256];
    const int tid = threadIdx.x;
    va[tid] = w_a[tid * 2 + 0] * a[2] + w_a[tid * 2 + 1] * a[3];
    __syncthreads();

    const int lane = tid & 31;
    const int warp = tid >> 5;
    const int row = blockIdx.x * 8 + warp;
    const float* hp = &g_hprime[(size_t)row * 256];

    float s = 0.f;
#pragma unroll
    for (int k = 0; k < 8; k++) {
        int c = lane + k * 32;
        s += hp[c] * va[c];
    }
#pragma unroll
    for (int o = 16; o > 0; o >>= 1) s += __shfl_xor_sync(0xffffffffu, s, o);
    if (lane == 0) g_fdst[row] = s;
}

// ---------------------------------------------------------------------------
// Kernel 3: per-row sparse softmax + aggregation + relu.
// One CTA (256 threads) per row. Deterministic compaction:
//   thread t scans cols [t*32, t*32+32), stages indices in smem, then a
//   shfl prefix-scan over per-thread counts produces a canonical ordered list.
// ---------------------------------------------------------------------------
__global__ __launch_bounds__(256) void attn_kernel(const float* __restrict__ Ahat,
                                                   float* __restrict__ out) {
    __shared__ int   s_tmp[256 * 32];   // 32 KB staging
    __shared__ int   s_idx[MAXNN];
    __shared__ float s_w[MAXNN];
    __shared__ float s_red[256];
    __shared__ int   s_wsum[8];

    const int tid = threadIdx.x;
    const size_t row = blockIdx.x;
    const int lane = tid & 31;
    const int wid = tid >> 5;

    // --- scan: each thread owns 32 contiguous columns (8 x float4) ---
    const float4* arow = (const float4*)(Ahat + row * NN);
    int cnt = 0;
    const int base_col = tid * 32;
#pragma unroll
    for (int k = 0; k < 8; k++) {
        float4 v = arow[tid * 8 + k];
        int col = base_col + k * 4;
        if (v.x > 0.f) s_tmp[tid * 32 + cnt++] = col + 0;
        if (v.y > 0.f) s_tmp[tid * 32 + cnt++] = col + 1;
        if (v.z > 0.f) s_tmp[tid * 32 + cnt++] = col + 2;
        if (v.w > 0.f) s_tmp[tid * 32 + cnt++] = col + 3;
    }

    // --- exclusive prefix scan over per-thread counts (deterministic order) ---
    int v = cnt;
#pragma unroll
    for (int o = 1; o < 32; o <<= 1) {
        int n = __shfl_up_sync(0xffffffffu, v, o);
        if (lane >= o) v += n;
    }
    if (lane == 31) s_wsum[wid] = v;
    __syncthreads();
    if (tid < 8) {
        int x = s_wsum[tid];
#pragma unroll
        for (int o = 1; o < 8; o <<= 1) {
            int n = __shfl_up_sync(0xffu, x, o);
            if (tid >= o) x += n;
        }
        s_wsum[tid] = x;
    }
    __syncthreads();
    int excl = v - cnt + (wid ? s_wsum[wid - 1] : 0);
    int total = s_wsum[7];

    for (int i = 0; i < cnt; i++) {
        int p = excl + i;
        if (p < MAXNN) s_idx[p] = s_tmp[tid * 32 + i];
    }
    __syncthreads();
    int nnz = total < MAXNN ? total : MAXNN;

    // --- softmax over neighbor set (f_src cancels; masked exps are exactly 0) ---
    float lm = -3.4e38f;
    for (int j = tid; j < nnz; j += 256) {
        float f = g_fdst[s_idx[j]];
        s_w[j] = f;
        lm = fmaxf(lm, f);
    }
    s_red[tid] = lm;
    __syncthreads();
#pragma unroll
    for (int o = 128; o > 0; o >>= 1) {
        if (tid < o) s_red[tid] = fmaxf(s_red[tid], s_red[tid + o]);
        __syncthreads();
    }
    float m = s_red[0];
    __syncthreads();

    float ls = 0.f;
    for (int j = tid; j < nnz; j += 256) {
        float e = __expf(s_w[j] - m);
        s_w[j] = e;
        ls += e;
    }
    s_red[tid] = ls;
    __syncthreads();
#pragma unroll
    for (int o = 128; o > 0; o >>= 1) {
        if (tid < o) s_red[tid] += s_red[tid + o];
        __syncthreads();
    }
    float inv = 1.f / s_red[0];
    __syncthreads();

    // --- aggregation: thread tid owns column tid; coalesced L2-resident gather ---
    float a0 = 0.f, a1 = 0.f, a2 = 0.f, a3 = 0.f;
    int j = 0;
    for (; j + 4 <= nnz; j += 4) {
        a0 += s_w[j + 0] * g_hprime[(size_t)s_idx[j + 0] * 256 + tid];
        a1 += s_w[j + 1] * g_hprime[(size_t)s_idx[j + 1] * 256 + tid];
        a2 += s_w[j + 2] * g_hprime[(size_t)s_idx[j + 2] * 256 + tid];
        a3 += s_w[j + 3] * g_hprime[(size_t)s_idx[j + 3] * 256 + tid];
    }
    for (; j < nnz; j++)
        a0 += s_w[j] * g_hprime[(size_t)s_idx[j] * 256 + tid];

    float r = (a0 + a1) + (a2 + a3);
    out[row * 256 + tid] = fmaxf(r * inv, 0.f);
}

// ---------------------------------------------------------------------------
extern "C" void kernel_launch(void* const* d_in, const int* in_sizes, int n_in,
                              void* d_out, int out_size) {
    (void)in_sizes; (void)n_in; (void)out_size;
    const float* node = (const float*)d_in[0];
    const float* Ahat = (const float*)d_in[1];
    const float* w    = (const float*)d_in[2];
    const float* w_a  = (const float*)d_in[3];
    const float* a    = (const float*)d_in[4];
    float* out = (float*)d_out;

    dim3 ggrid(2, 64);
    gemm_kernel<<<ggrid, 256>>>(node, w);
    fdst_kernel<<<NN / 8, 256>>>(w_a, a);
    attn_kernel<<<NN, 256>>>(Ahat, out);
}

// round 4
// speedup vs baseline: 1.3868x; 1.3868x over previous
#include <cuda_runtime.h>
#include <cstddef>

#define NN 8192
#define FF 256
#define CAP 256      // per-warp (1024-col segment) neighbor cap; mean 10.3, 75+ sigma safe
#define MAXT 1024    // per-row total cap; mean 83

__device__ float g_hprime[(size_t)NN * FF];
__device__ float g_P[(size_t)NN * FF];
__device__ float g_fdst[NN];
__device__ float g_gv[NN];
__device__ unsigned g_maxbits;

// monotonic float->unsigned key
__device__ __forceinline__ unsigned fkey(float f) {
    unsigned b = __float_as_uint(f);
    return b ^ ((b & 0x80000000u) ? 0xFFFFFFFFu : 0x80000000u);
}
__device__ __forceinline__ float funkey(unsigned k) {
    unsigned b = (k & 0x80000000u) ? (k ^ 0x80000000u) : (k ^ 0xFFFFFFFFu);
    return __uint_as_float(b);
}

// ---------------------------------------------------------------------------
// Kernel 1: h_prime = node_feats @ w  (8192x256x256 fp32)
// 128x64 tile, 256 threads, 8x4 microtile, K-chunks of 16. grid = 4 x 64 = 256 CTAs.
// ---------------------------------------------------------------------------
__global__ __launch_bounds__(256) void gemm_kernel(const float* __restrict__ A,
                                                   const float* __restrict__ W) {
    __shared__ float As[16][128];
    __shared__ float Bs[16][64];

    const int m0 = blockIdx.y * 128;
    const int n0 = blockIdx.x * 64;
    const int tid = threadIdx.x;

    if (blockIdx.x == 0 && blockIdx.y == 0 && tid == 0) g_maxbits = 0u;  // key(very -f)

    const int tr = tid >> 4;        // 0..15 (M group of 8)
    const int tc = tid & 15;        // 0..15 (N group of 4)

    const int ar = tid >> 1;        // 0..127
    const int ac = (tid & 1) * 8;   // 0 or 8
    const int br = tid >> 4;        // 0..15
    const int bc = (tid & 15) * 4;  // 0..60

    float acc[8][4];
#pragma unroll
    for (int i = 0; i < 8; i++)
#pragma unroll
        for (int j = 0; j < 4; j++) acc[i][j] = 0.f;

    for (int k0 = 0; k0 < 256; k0 += 16) {
        float4 a0 = *(const float4*)&A[(size_t)(m0 + ar) * 256 + k0 + ac];
        float4 a1 = *(const float4*)&A[(size_t)(m0 + ar) * 256 + k0 + ac + 4];
        float4 b0 = *(const float4*)&W[(size_t)(k0 + br) * 256 + n0 + bc];

        __syncthreads();
        As[ac + 0][ar] = a0.x; As[ac + 1][ar] = a0.y;
        As[ac + 2][ar] = a0.z; As[ac + 3][ar] = a0.w;
        As[ac + 4][ar] = a1.x; As[ac + 5][ar] = a1.y;
        As[ac + 6][ar] = a1.z; As[ac + 7][ar] = a1.w;
        *(float4*)&Bs[br][bc] = b0;
        __syncthreads();

#pragma unroll
        for (int k = 0; k < 16; k++) {
            float4 x0 = *(const float4*)&As[k][tr * 8];
            float4 x1 = *(const float4*)&As[k][tr * 8 + 4];
            float4 y0 = *(const float4*)&Bs[k][tc * 4];
            float ra[8] = {x0.x, x0.y, x0.z, x0.w, x1.x, x1.y, x1.z, x1.w};
            float rb[4] = {y0.x, y0.y, y0.z, y0.w};
#pragma unroll
            for (int i = 0; i < 8; i++)
#pragma unroll
                for (int j = 0; j < 4; j++) acc[i][j] += ra[i] * rb[j];
        }
    }

#pragma unroll
    for (int i = 0; i < 8; i++) {
        float* dst = &g_hprime[(size_t)(m0 + tr * 8 + i) * 256 + n0 + tc * 4];
        *(float4*)dst = make_float4(acc[i][0], acc[i][1], acc[i][2], acc[i][3]);
    }
}

// ---------------------------------------------------------------------------
// Kernel 2: f_dst[j] = h_prime[j,:] . (w_a @ a[2:4]); also global max via
// atomicMax (order-independent => deterministic).
// (f_src cancels in the row softmax.)
// ---------------------------------------------------------------------------
__global__ __launch_bounds__(256) void fdst_kernel(const float* __restrict__ w_a,
                                                   const float* __restrict__ a) {
    __shared__ float va[256];
    __shared__ float s_f[8];
    const int tid = threadIdx.x;
    va[tid] = w_a[tid * 2 + 0] * a[2] + w_a[tid * 2 + 1] * a[3];
    __syncthreads();

    const int lane = tid & 31;
    const int warp = tid >> 5;
    const int row = blockIdx.x * 8 + warp;
    const float* hp = &g_hprime[(size_t)row * 256];

    float s = 0.f;
#pragma unroll
    for (int k = 0; k < 8; k++) {
        int c = lane + k * 32;
        s += hp[c] * va[c];
    }
#pragma unroll
    for (int o = 16; o > 0; o >>= 1) s += __shfl_xor_sync(0xffffffffu, s, o);
    if (lane == 0) { g_fdst[row] = s; s_f[warp] = s; }
    __syncthreads();
    if (tid == 0) {
        float m = s_f[0];
#pragma unroll
        for (int w = 1; w < 8; w++) m = fmaxf(m, s_f[w]);
        atomicMax(&g_maxbits, fkey(m));
    }
}

// ---------------------------------------------------------------------------
// Kernel 3: g[j] = exp(f_dst[j]-M);  P[j,:] = g[j] * h_prime[j,:]
// ---------------------------------------------------------------------------
__global__ __launch_bounds__(256) void pmul_kernel() {
    const int tid = threadIdx.x;
    const float M = funkey(g_maxbits);
#pragma unroll
    for (int r = 0; r < 16; r++) {
        const int row = blockIdx.x * 16 + r;
        const float gv = __expf(g_fdst[row] - M);
        g_P[(size_t)row * 256 + tid] = g_hprime[(size_t)row * 256 + tid] * gv;
        if (tid == 0) g_gv[row] = gv;
    }
}

// ---------------------------------------------------------------------------
// Kernel 4: per-row scan + aggregation + relu.
// out[i] = relu( sum_{j in N(i)} P[j] / sum_{j in N(i)} g[j] )
// One CTA (256 thr) per row. Warp w scans cols [w*1024,(w+1)*1024) with
// ballot compaction (deterministic order). Denominator accumulated in-scan.
// ---------------------------------------------------------------------------
__global__ __launch_bounds__(256) void attn_kernel(const float* __restrict__ Ahat,
                                                   float* __restrict__ out) {
    __shared__ int   s_seg[8 * CAP];   // 8 KB
    __shared__ int   s_flat[MAXT];     // 4 KB
    __shared__ int   s_cnt[8];
    __shared__ float s_den[8];
    __shared__ int   s_off[9];

    const int tid = threadIdx.x;
    const int lane = tid & 31;
    const int wid = tid >> 5;
    const size_t row = blockIdx.x;

    const float4* arow = (const float4*)(Ahat + row * NN);
    const int base = wid * 1024;

    int cnt = 0;
    float denl = 0.f;
#pragma unroll
    for (int it = 0; it < 8; it++) {
        float4 v = arow[wid * 256 + it * 32 + lane];
        const int col = base + it * 128 + lane * 4;
        const unsigned lt = (1u << lane) - 1u;

        {   bool p = v.x > 0.f; unsigned m = __ballot_sync(0xffffffffu, p);
            if (p) { int pos = cnt + __popc(m & lt);
                     if (pos < CAP) s_seg[wid * CAP + pos] = col;
                     denl += g_gv[col]; }
            cnt += __popc(m); }
        {   bool p = v.y > 0.f; unsigned m = __ballot_sync(0xffffffffu, p);
            if (p) { int pos = cnt + __popc(m & lt);
                     if (pos < CAP) s_seg[wid * CAP + pos] = col + 1;
                     denl += g_gv[col + 1]; }
            cnt += __popc(m); }
        {   bool p = v.z > 0.f; unsigned m = __ballot_sync(0xffffffffu, p);
            if (p) { int pos = cnt + __popc(m & lt);
                     if (pos < CAP) s_seg[wid * CAP + pos] = col + 2;
                     denl += g_gv[col + 2]; }
            cnt += __popc(m); }
        {   bool p = v.w > 0.f; unsigned m = __ballot_sync(0xffffffffu, p);
            if (p) { int pos = cnt + __popc(m & lt);
                     if (pos < CAP) s_seg[wid * CAP + pos] = col + 3;
                     denl += g_gv[col + 3]; }
            cnt += __popc(m); }
    }

#pragma unroll
    for (int o = 16; o > 0; o >>= 1) denl += __shfl_xor_sync(0xffffffffu, denl, o);
    if (lane == 0) { s_cnt[wid] = (cnt < CAP ? cnt : CAP); s_den[wid] = denl; }
    __syncthreads();

    if (tid == 0) {
        int o = 0;
#pragma unroll
        for (int w = 0; w < 8; w++) { s_off[w] = o; o += s_cnt[w]; }
        s_off[8] = o;
    }
    __syncthreads();

    {   const int c = s_cnt[wid];
        const int o = s_off[wid];
        for (int j = lane; j < c; j += 32)
            if (o + j < MAXT) s_flat[o + j] = s_seg[wid * CAP + j];
    }
    __syncthreads();

    int nnz = s_off[8]; if (nnz > MAXT) nnz = MAXT;
    float den = s_den[0] + s_den[1] + s_den[2] + s_den[3] +
                s_den[4] + s_den[5] + s_den[6] + s_den[7];

    // add-only gather: thread tid owns column tid; 8-way MLP
    float a0 = 0.f, a1 = 0.f, a2 = 0.f, a3 = 0.f,
          a4 = 0.f, a5 = 0.f, a6 = 0.f, a7 = 0.f;
    int j = 0;
    for (; j + 8 <= nnz; j += 8) {
        a0 += g_P[(size_t)s_flat[j + 0] * 256 + tid];
        a1 += g_P[(size_t)s_flat[j + 1] * 256 + tid];
        a2 += g_P[(size_t)s_flat[j + 2] * 256 + tid];
        a3 += g_P[(size_t)s_flat[j + 3] * 256 + tid];
        a4 += g_P[(size_t)s_flat[j + 4] * 256 + tid];
        a5 += g_P[(size_t)s_flat[j + 5] * 256 + tid];
        a6 += g_P[(size_t)s_flat[j + 6] * 256 + tid];
        a7 += g_P[(size_t)s_flat[j + 7] * 256 + tid];
    }
    for (; j < nnz; j++) a0 += g_P[(size_t)s_flat[j] * 256 + tid];

    float r = ((a0 + a1) + (a2 + a3)) + ((a4 + a5) + (a6 + a7));
    out[row * 256 + tid] = fmaxf(r / den, 0.f);
}

// ---------------------------------------------------------------------------
extern "C" void kernel_launch(void* const* d_in, const int* in_sizes, int n_in,
                              void* d_out, int out_size) {
    (void)in_sizes; (void)n_in; (void)out_size;
    const float* node = (const float*)d_in[0];
    const float* Ahat = (const float*)d_in[1];
    const float* w    = (const float*)d_in[2];
    const float* w_a  = (const float*)d_in[3];
    const float* a    = (const float*)d_in[4];
    float* out = (float*)d_out;

    dim3 ggrid(4, 64);
    gemm_kernel<<<ggrid, 256>>>(node, w);
    fdst_kernel<<<NN / 8, 256>>>(w_a, a);
    pmul_kernel<<<NN / 16, 256>>>();
    attn_kernel<<<NN, 256>>>(Ahat, out);
}

// round 8
// speedup vs baseline: 1.4020x; 1.0110x over previous
#include <cuda_runtime.h>
#include <cstddef>

#define NN 8192
#define FF 256
#define MAXT 1024    // per-row total neighbor cap; mean 83

__device__ float g_hprime[(size_t)NN * FF];
__device__ float g_P[(size_t)NN * FF];
__device__ float g_fdst[NN];
__device__ float g_gv[NN];
__device__ unsigned g_maxbits;

__device__ __forceinline__ unsigned fkey(float f) {
    unsigned b = __float_as_uint(f);
    return b ^ ((b & 0x80000000u) ? 0xFFFFFFFFu : 0x80000000u);
}
__device__ __forceinline__ float funkey(unsigned k) {
    unsigned b = (k & 0x80000000u) ? (k ^ 0x80000000u) : (k ^ 0xFFFFFFFFu);
    return __uint_as_float(b);
}

// ---------------------------------------------------------------------------
// Kernel 1: h_prime = node_feats @ w  (8192x256x256 fp32)
// 128x64 tile, 256 threads, 8x4 microtile. grid = 4 x 64 = 256 CTAs.
// ---------------------------------------------------------------------------
__global__ __launch_bounds__(256) void gemm_kernel(const float* __restrict__ A,
                                                   const float* __restrict__ W) {
    __shared__ float As[16][128];
    __shared__ float Bs[16][64];

    const int m0 = blockIdx.y * 128;
    const int n0 = blockIdx.x * 64;
    const int tid = threadIdx.x;

    if (blockIdx.x == 0 && blockIdx.y == 0 && tid == 0) g_maxbits = 0u;

    const int tr = tid >> 4;
    const int tc = tid & 15;
    const int ar = tid >> 1;
    const int ac = (tid & 1) * 8;
    const int br = tid >> 4;
    const int bc = (tid & 15) * 4;

    float acc[8][4];
#pragma unroll
    for (int i = 0; i < 8; i++)
#pragma unroll
        for (int j = 0; j < 4; j++) acc[i][j] = 0.f;

    for (int k0 = 0; k0 < 256; k0 += 16) {
        float4 a0 = *(const float4*)&A[(size_t)(m0 + ar) * 256 + k0 + ac];
        float4 a1 = *(const float4*)&A[(size_t)(m0 + ar) * 256 + k0 + ac + 4];
        float4 b0 = *(const float4*)&W[(size_t)(k0 + br) * 256 + n0 + bc];

        __syncthreads();
        As[ac + 0][ar] = a0.x; As[ac + 1][ar] = a0.y;
        As[ac + 2][ar] = a0.z; As[ac + 3][ar] = a0.w;
        As[ac + 4][ar] = a1.x; As[ac + 5][ar] = a1.y;
        As[ac + 6][ar] = a1.z; As[ac + 7][ar] = a1.w;
        *(float4*)&Bs[br][bc] = b0;
        __syncthreads();

#pragma unroll
        for (int k = 0; k < 16; k++) {
            float4 x0 = *(const float4*)&As[k][tr * 8];
            float4 x1 = *(const float4*)&As[k][tr * 8 + 4];
            float4 y0 = *(const float4*)&Bs[k][tc * 4];
            float ra[8] = {x0.x, x0.y, x0.z, x0.w, x1.x, x1.y, x1.z, x1.w};
            float rb[4] = {y0.x, y0.y, y0.z, y0.w};
#pragma unroll
            for (int i = 0; i < 8; i++)
#pragma unroll
                for (int j = 0; j < 4; j++) acc[i][j] += ra[i] * rb[j];
        }
    }

#pragma unroll
    for (int i = 0; i < 8; i++) {
        float* dst = &g_hprime[(size_t)(m0 + tr * 8 + i) * 256 + n0 + tc * 4];
        *(float4*)dst = make_float4(acc[i][0], acc[i][1], acc[i][2], acc[i][3]);
    }
}

// ---------------------------------------------------------------------------
// Kernel 2: f_dst[j] = h_prime[j,:] . (w_a @ a[2:4]); global max via atomicMax
// on monotone key (order-independent => deterministic). f_src cancels in the
// row softmax.
// ---------------------------------------------------------------------------
__global__ __launch_bounds__(256) void fdst_kernel(const float* __restrict__ w_a,
                                                   const float* __restrict__ a) {
    __shared__ float va[256];
    __shared__ float s_f[8];
    const int tid = threadIdx.x;
    va[tid] = w_a[tid * 2 + 0] * a[2] + w_a[tid * 2 + 1] * a[3];
    __syncthreads();

    const int lane = tid & 31;
    const int warp = tid >> 5;
    const int row = blockIdx.x * 8 + warp;
    const float* hp = &g_hprime[(size_t)row * 256];

    float s = 0.f;
#pragma unroll
    for (int k = 0; k < 8; k++) {
        int c = lane + k * 32;
        s += hp[c] * va[c];
    }
#pragma unroll
    for (int o = 16; o > 0; o >>= 1) s += __shfl_xor_sync(0xffffffffu, s, o);
    if (lane == 0) { g_fdst[row] = s; s_f[warp] = s; }
    __syncthreads();
    if (tid == 0) {
        float m = s_f[0];
#pragma unroll
        for (int w = 1; w < 8; w++) m = fmaxf(m, s_f[w]);
        atomicMax(&g_maxbits, fkey(m));
    }
}

// ---------------------------------------------------------------------------
// Kernel 3: g[j] = exp(f_dst[j]-M);  P[j,:] = g[j]*h_prime[j,:]  (float4)
// 4 rows per CTA, 64 threads per row.
// ---------------------------------------------------------------------------
__global__ __launch_bounds__(256) void pmul_kernel() {
    const int tid = threadIdx.x;
    const int row = blockIdx.x * 4 + (tid >> 6);
    const int c = tid & 63;
    const float M = funkey(g_maxbits);
    const float gv = __expf(g_fdst[row] - M);
    float4 h = *((const float4*)&g_hprime[(size_t)row * 256] + c);
    h.x *= gv; h.y *= gv; h.z *= gv; h.w *= gv;
    *((float4*)&g_P[(size_t)row * 256] + c) = h;
    if (c == 0) g_gv[row] = gv;
}

// ---------------------------------------------------------------------------
// Kernel 4: per-row scan + aggregation + relu.
// out[i] = relu( sum_{j in N(i)} P[j] / sum_{j in N(i)} g[j] )
// One CTA (256 thr) per row.
//  Phase A: thread t builds 32-bit presence mask of cols [t*32, t*32+32),
//           warp+CTA prefix scan over popc, ffs-extraction writes a canonical
//           ascending index list to s_flat (deterministic).
//  Phase B: 4 groups x 64 threads; group g aggregates neighbors j==g (mod 4)
//           with float4 loads (4x fewer LDG issues); smem cross-group add.
// ---------------------------------------------------------------------------
__global__ __launch_bounds__(256) void attn_kernel(const float* __restrict__ Ahat,
                                                   float* __restrict__ out) {
    __shared__ int   s_flat[MAXT];      // 4 KB
    __shared__ float s_part[4 * 256];   // 4 KB
    __shared__ int   s_cnt[8];
    __shared__ float s_den[8];
    __shared__ int   s_off[9];

    const int tid = threadIdx.x;
    const int lane = tid & 31;
    const int wid = tid >> 5;
    const size_t row = blockIdx.x;

    // --- Phase A: presence mask (streaming loads) ---
    const float4* arow = (const float4*)(Ahat + row * NN);
    unsigned mask = 0u;
#pragma unroll
    for (int k = 0; k < 8; k++) {
        float4 v = __ldcs(&arow[tid * 8 + k]);
        if (v.x > 0.f) mask |= 1u << (4 * k + 0);
        if (v.y > 0.f) mask |= 1u << (4 * k + 1);
        if (v.z > 0.f) mask |= 1u << (4 * k + 2);
        if (v.w > 0.f) mask |= 1u << (4 * k + 3);
    }
    int cnt = __popc(mask);

    // warp inclusive prefix scan over counts
    int pre = cnt;
#pragma unroll
    for (int o = 1; o < 32; o <<= 1) {
        int n = __shfl_up_sync(0xffffffffu, pre, o);
        if (lane >= o) pre += n;
    }
    if (lane == 31) s_cnt[wid] = pre;
    __syncthreads();
    if (tid == 0) {
        int o = 0;
#pragma unroll
        for (int w = 0; w < 8; w++) { s_off[w] = o; o += s_cnt[w]; }
        s_off[8] = o;
    }
    __syncthreads();

    // extraction: canonical ascending order; accumulate denominator in-scan
    int off = s_off[wid] + (pre - cnt);
    float denl = 0.f;
    const int cbase = tid * 32;
    unsigned m = mask;
    while (m) {
        int b = __ffs(m) - 1;
        int col = cbase + b;
        if (off < MAXT) s_flat[off] = col;
        off++;
        denl += g_gv[col];
        m &= m - 1u;
    }

#pragma unroll
    for (int o = 16; o > 0; o >>= 1) denl += __shfl_xor_sync(0xffffffffu, denl, o);
    if (lane == 0) s_den[wid] = denl;
    __syncthreads();

    int nnz = s_off[8]; if (nnz > MAXT) nnz = MAXT;
    float den = ((s_den[0] + s_den[1]) + (s_den[2] + s_den[3])) +
                ((s_den[4] + s_den[5]) + (s_den[6] + s_den[7]));

    // --- Phase B: grouped float4 gather ---
    const int g = tid >> 6;    // group 0..3
    const int c = tid & 63;    // float4 column index 0..63

    float4 a0 = make_float4(0.f, 0.f, 0.f, 0.f);
    float4 a1 = make_float4(0.f, 0.f, 0.f, 0.f);
    float4 a2 = make_float4(0.f, 0.f, 0.f, 0.f);
    float4 a3 = make_float4(0.f, 0.f, 0.f, 0.f);

    int j = g;
    for (; j + 12 < nnz; j += 16) {
        float4 v0 = __ldg((const float4*)&g_P[(size_t)s_flat[j + 0]  * 256] + c);
        float4 v1 = __ldg((const float4*)&g_P[(size_t)s_flat[j + 4]  * 256] + c);
        float4 v2 = __ldg((const float4*)&g_P[(size_t)s_flat[j + 8]  * 256] + c);
        float4 v3 = __ldg((const float4*)&g_P[(size_t)s_flat[j + 12] * 256] + c);
        a0.x += v0.x; a0.y += v0.y; a0.z += v0.z; a0.w += v0.w;
        a1.x += v1.x; a1.y += v1.y; a1.z += v1.z; a1.w += v1.w;
        a2.x += v2.x; a2.y += v2.y; a2.z += v2.z; a2.w += v2.w;
        a3.x += v3.x; a3.y += v3.y; a3.z += v3.z; a3.w += v3.w;
    }
    for (; j < nnz; j += 4) {
        float4 v0 = __ldg((const float4*)&g_P[(size_t)s_flat[j] * 256] + c);
        a0.x += v0.x; a0.y += v0.y; a0.z += v0.z; a0.w += v0.w;
    }
    a0.x = (a0.x + a1.x) + (a2.x + a3.x);
    a0.y = (a0.y + a1.y) + (a2.y + a3.y);
    a0.z = (a0.z + a1.z) + (a2.z + a3.z);
    a0.w = (a0.w + a1.w) + (a2.w + a3.w);

    *((float4*)&s_part[g * 256] + c) = a0;
    __syncthreads();

    // final cross-group reduction + relu; thread tid owns column tid
    float r = ((s_part[0 * 256 + tid] + s_part[1 * 256 + tid]) +
               (s_part[2 * 256 + tid] + s_part[3 * 256 + tid]));
    out[row * 256 + tid] = fmaxf(r / den, 0.f);
}

// ---------------------------------------------------------------------------
extern "C" void kernel_launch(void* const* d_in, const int* in_sizes, int n_in,
                              void* d_out, int out_size) {
    (void)in_sizes; (void)n_in; (void)out_size;
    const float* node = (const float*)d_in[0];
    const float* Ahat = (const float*)d_in[1];
    const float* w    = (const float*)d_in[2];
    const float* w_a  = (const float*)d_in[3];
    const float* a    = (const float*)d_in[4];
    float* out = (float*)d_out;

    dim3 ggrid(4, 64);
    gemm_kernel<<<ggrid, 256>>>(node, w);
    fdst_kernel<<<NN / 8, 256>>>(w_a, a);
    pmul_kernel<<<NN / 4, 256>>>();
    attn_kernel<<<NN, 256>>>(Ahat, out);
}

// round 9
// speedup vs baseline: 1.8424x; 1.3141x over previous
#include <cuda_runtime.h>
#include <cstddef>

#define NN 8192
#define FF 256
#define MAXT 1024    // per-row total neighbor cap; mean 83

__device__ float g_hprime[(size_t)NN * FF];
__device__ float g_P[(size_t)NN * FF];
__device__ float g_fdst[NN];
__device__ float g_gv[NN];
__device__ unsigned g_maxbits;

__device__ __forceinline__ unsigned fkey(float f) {
    unsigned b = __float_as_uint(f);
    return b ^ ((b & 0x80000000u) ? 0xFFFFFFFFu : 0x80000000u);
}
__device__ __forceinline__ float funkey(unsigned k) {
    unsigned b = (k & 0x80000000u) ? (k ^ 0x80000000u) : (k ^ 0xFFFFFFFFu);
    return __uint_as_float(b);
}

// ---------------------------------------------------------------------------
// Kernel 1: h_prime = node_feats @ w  (8192x256x256 fp32)
// 128x64 tile, 256 threads, 8x4 microtile. grid = 4 x 64 = 256 CTAs.
// ---------------------------------------------------------------------------
__global__ __launch_bounds__(256) void gemm_kernel(const float* __restrict__ A,
                                                   const float* __restrict__ W) {
    __shared__ float As[16][128];
    __shared__ float Bs[16][64];

    const int m0 = blockIdx.y * 128;
    const int n0 = blockIdx.x * 64;
    const int tid = threadIdx.x;

    if (blockIdx.x == 0 && blockIdx.y == 0 && tid == 0) g_maxbits = 0u;

    const int tr = tid >> 4;
    const int tc = tid & 15;
    const int ar = tid >> 1;
    const int ac = (tid & 1) * 8;
    const int br = tid >> 4;
    const int bc = (tid & 15) * 4;

    float acc[8][4];
#pragma unroll
    for (int i = 0; i < 8; i++)
#pragma unroll
        for (int j = 0; j < 4; j++) acc[i][j] = 0.f;

    for (int k0 = 0; k0 < 256; k0 += 16) {
        float4 a0 = *(const float4*)&A[(size_t)(m0 + ar) * 256 + k0 + ac];
        float4 a1 = *(const float4*)&A[(size_t)(m0 + ar) * 256 + k0 + ac + 4];
        float4 b0 = *(const float4*)&W[(size_t)(k0 + br) * 256 + n0 + bc];

        __syncthreads();
        As[ac + 0][ar] = a0.x; As[ac + 1][ar] = a0.y;
        As[ac + 2][ar] = a0.z; As[ac + 3][ar] = a0.w;
        As[ac + 4][ar] = a1.x; As[ac + 5][ar] = a1.y;
        As[ac + 6][ar] = a1.z; As[ac + 7][ar] = a1.w;
        *(float4*)&Bs[br][bc] = b0;
        __syncthreads();

#pragma unroll
        for (int k = 0; k < 16; k++) {
            float4 x0 = *(const float4*)&As[k][tr * 8];
            float4 x1 = *(const float4*)&As[k][tr * 8 + 4];
            float4 y0 = *(const float4*)&Bs[k][tc * 4];
            float ra[8] = {x0.x, x0.y, x0.z, x0.w, x1.x, x1.y, x1.z, x1.w};
            float rb[4] = {y0.x, y0.y, y0.z, y0.w};
#pragma unroll
            for (int i = 0; i < 8; i++)
#pragma unroll
                for (int j = 0; j < 4; j++) acc[i][j] += ra[i] * rb[j];
        }
    }

#pragma unroll
    for (int i = 0; i < 8; i++) {
        float* dst = &g_hprime[(size_t)(m0 + tr * 8 + i) * 256 + n0 + tc * 4];
        *(float4*)dst = make_float4(acc[i][0], acc[i][1], acc[i][2], acc[i][3]);
    }
}

// ---------------------------------------------------------------------------
// Kernel 2: f_dst[j] = h_prime[j,:] . (w_a @ a[2:4]); global max via atomicMax
// on monotone key (order-independent => deterministic). f_src cancels in the
// row softmax.
// ---------------------------------------------------------------------------
__global__ __launch_bounds__(256) void fdst_kernel(const float* __restrict__ w_a,
                                                   const float* __restrict__ a) {
    __shared__ float va[256];
    __shared__ float s_f[8];
    const int tid = threadIdx.x;
    va[tid] = w_a[tid * 2 + 0] * a[2] + w_a[tid * 2 + 1] * a[3];
    __syncthreads();

    const int lane = tid & 31;
    const int warp = tid >> 5;
    const int row = blockIdx.x * 8 + warp;
    const float* hp = &g_hprime[(size_t)row * 256];

    float s = 0.f;
#pragma unroll
    for (int k = 0; k < 8; k++) {
        int c = lane + k * 32;
        s += hp[c] * va[c];
    }
#pragma unroll
    for (int o = 16; o > 0; o >>= 1) s += __shfl_xor_sync(0xffffffffu, s, o);
    if (lane == 0) { g_fdst[row] = s; s_f[warp] = s; }
    __syncthreads();
    if (tid == 0) {
        float m = s_f[0];
#pragma unroll
        for (int w = 1; w < 8; w++) m = fmaxf(m, s_f[w]);
        atomicMax(&g_maxbits, fkey(m));
    }
}

// ---------------------------------------------------------------------------
// Kernel 3: g[j] = exp(f_dst[j]-M);  P[j,:] = g[j]*h_prime[j,:]  (float4)
// 4 rows per CTA, 64 threads per row.
// ---------------------------------------------------------------------------
__global__ __launch_bounds__(256) void pmul_kernel() {
    const int tid = threadIdx.x;
    const int row = blockIdx.x * 4 + (tid >> 6);
    const int c = tid & 63;
    const float M = funkey(g_maxbits);
    const float gv = __expf(g_fdst[row] - M);
    float4 h = *((const float4*)&g_hprime[(size_t)row * 256] + c);
    h.x *= gv; h.y *= gv; h.z *= gv; h.w *= gv;
    *((float4*)&g_P[(size_t)row * 256] + c) = h;
    if (c == 0) g_gv[row] = gv;
}

// ---------------------------------------------------------------------------
// Kernel 4: per-row scan + aggregation + relu.
// out[i] = relu( sum_{j in N(i)} P[j] / sum_{j in N(i)} g[j] )
// One CTA (256 thr) per row.
//  Phase A (COALESCED): warp w owns cols [w*1024,(w+1)*1024). Lane l iter k
//    loads float4 at arow4[w*256 + k*32 + l] -> consecutive lanes contiguous
//    (512B/warp/LDG, 4 wavefronts instead of 32). Presence-mask bit b=4k+c
//    maps to col = w*1024 + (b>>2)*128 + l*4 + (b&3). Extraction order is a
//    fixed canonical (not globally ascending) order -> deterministic.
//  Phase B: 4 groups x 64 threads; group g aggregates neighbors j==g (mod 4)
//    with float4 loads; smem cross-group add.
// ---------------------------------------------------------------------------
__global__ __launch_bounds__(256) void attn_kernel(const float* __restrict__ Ahat,
                                                   float* __restrict__ out) {
    __shared__ int   s_flat[MAXT];      // 4 KB
    __shared__ float s_part[4 * 256];   // 4 KB
    __shared__ int   s_cnt[8];
    __shared__ float s_den[8];
    __shared__ int   s_off[9];

    const int tid = threadIdx.x;
    const int lane = tid & 31;
    const int wid = tid >> 5;
    const size_t row = blockIdx.x;

    // --- Phase A: coalesced presence-mask scan ---
    const float4* arow = (const float4*)(Ahat + row * NN);
    unsigned mask = 0u;
#pragma unroll
    for (int k = 0; k < 8; k++) {
        float4 v = __ldcs(&arow[wid * 256 + k * 32 + lane]);
        if (v.x > 0.f) mask |= 1u << (4 * k + 0);
        if (v.y > 0.f) mask |= 1u << (4 * k + 1);
        if (v.z > 0.f) mask |= 1u << (4 * k + 2);
        if (v.w > 0.f) mask |= 1u << (4 * k + 3);
    }
    int cnt = __popc(mask);

    // warp inclusive prefix scan over per-lane counts
    int pre = cnt;
#pragma unroll
    for (int o = 1; o < 32; o <<= 1) {
        int n = __shfl_up_sync(0xffffffffu, pre, o);
        if (lane >= o) pre += n;
    }
    if (lane == 31) s_cnt[wid] = pre;
    __syncthreads();
    if (tid == 0) {
        int o = 0;
#pragma unroll
        for (int w = 0; w < 8; w++) { s_off[w] = o; o += s_cnt[w]; }
        s_off[8] = o;
    }
    __syncthreads();

    // extraction: canonical fixed order; accumulate denominator in-scan
    int off = s_off[wid] + (pre - cnt);
    float denl = 0.f;
    const int cbase = wid * 1024 + lane * 4;
    unsigned m = mask;
    while (m) {
        int b = __ffs(m) - 1;
        int col = cbase + (b >> 2) * 128 + (b & 3);
        if (off < MAXT) s_flat[off] = col;
        off++;
        denl += g_gv[col];
        m &= m - 1u;
    }

#pragma unroll
    for (int o = 16; o > 0; o >>= 1) denl += __shfl_xor_sync(0xffffffffu, denl, o);
    if (lane == 0) s_den[wid] = denl;
    __syncthreads();

    int nnz = s_off[8]; if (nnz > MAXT) nnz = MAXT;
    float den = ((s_den[0] + s_den[1]) + (s_den[2] + s_den[3])) +
                ((s_den[4] + s_den[5]) + (s_den[6] + s_den[7]));

    // --- Phase B: grouped float4 gather ---
    const int g = tid >> 6;    // group 0..3
    const int c = tid & 63;    // float4 column index 0..63

    float4 a0 = make_float4(0.f, 0.f, 0.f, 0.f);
    float4 a1 = make_float4(0.f, 0.f, 0.f, 0.f);
    float4 a2 = make_float4(0.f, 0.f, 0.f, 0.f);
    float4 a3 = make_float4(0.f, 0.f, 0.f, 0.f);

    int j = g;
    for (; j + 12 < nnz; j += 16) {
        float4 v0 = __ldg((const float4*)&g_P[(size_t)s_flat[j + 0]  * 256] + c);
        float4 v1 = __ldg((const float4*)&g_P[(size_t)s_flat[j + 4]  * 256] + c);
        float4 v2 = __ldg((const float4*)&g_P[(size_t)s_flat[j + 8]  * 256] + c);
        float4 v3 = __ldg((const float4*)&g_P[(size_t)s_flat[j + 12] * 256] + c);
        a0.x += v0.x; a0.y += v0.y; a0.z += v0.z; a0.w += v0.w;
        a1.x += v1.x; a1.y += v1.y; a1.z += v1.z; a1.w += v1.w;
        a2.x += v2.x; a2.y += v2.y; a2.z += v2.z; a2.w += v2.w;
        a3.x += v3.x; a3.y += v3.y; a3.z += v3.z; a3.w += v3.w;
    }
    for (; j < nnz; j += 4) {
        float4 v0 = __ldg((const float4*)&g_P[(size_t)s_flat[j] * 256] + c);
        a0.x += v0.x; a0.y += v0.y; a0.z += v0.z; a0.w += v0.w;
    }
    a0.x = (a0.x + a1.x) + (a2.x + a3.x);
    a0.y = (a0.y + a1.y) + (a2.y + a3.y);
    a0.z = (a0.z + a1.z) + (a2.z + a3.z);
    a0.w = (a0.w + a1.w) + (a2.w + a3.w);

    *((float4*)&s_part[g * 256] + c) = a0;
    __syncthreads();

    // final cross-group reduction + relu; thread tid owns column tid
    float r = ((s_part[0 * 256 + tid] + s_part[1 * 256 + tid]) +
               (s_part[2 * 256 + tid] + s_part[3 * 256 + tid]));
    out[row * 256 + tid] = fmaxf(r / den, 0.f);
}

// ---------------------------------------------------------------------------
extern "C" void kernel_launch(void* const* d_in, const int* in_sizes, int n_in,
                              void* d_out, int out_size) {
    (void)in_sizes; (void)n_in; (void)out_size;
    const float* node = (const float*)d_in[0];
    const float* Ahat = (const float*)d_in[1];
    const float* w    = (const float*)d_in[2];
    const float* w_a  = (const float*)d_in[3];
    const float* a    = (const float*)d_in[4];
    float* out = (float*)d_out;

    dim3 ggrid(4, 64);
    gemm_kernel<<<ggrid, 256>>>(node, w);
    fdst_kernel<<<NN / 8, 256>>>(w_a, a);
    pmul_kernel<<<NN / 4, 256>>>();
    attn_kernel<<<NN, 256>>>(Ahat, out);
}

// round 12
// speedup vs baseline: 2.1540x; 1.1691x over previous
#include <cuda_runtime.h>
#include <cuda_fp16.h>
#include <cstddef>

#define NN 8192
#define FF 256
#define MAXT 1024     // per-row neighbor cap; mean 83
#define PSCALE 8192.0f

__device__ __half g_P[(size_t)NN * FF];   // P = PSCALE * exp(f-M) * h_prime  (fp16)
__device__ float  g_fdst[NN];
__device__ float  g_gv[NN];               // exp(f-M), fp32
__device__ float  g_wv[FF];               // w @ (w_a @ a[2:4])
__device__ unsigned g_maxbits;

__device__ __forceinline__ unsigned fkey(float f) {
    unsigned b = __float_as_uint(f);
    return b ^ ((b & 0x80000000u) ? 0xFFFFFFFFu : 0x80000000u);
}
__device__ __forceinline__ float funkey(unsigned k) {
    unsigned b = (k & 0x80000000u) ? (k ^ 0x80000000u) : (k ^ 0xFFFFFFFFu);
    return __uint_as_float(b);
}

// ---------------------------------------------------------------------------
// Kernel 0: wv[k] = sum_o w[k,o] * va[o]   where va = w_a @ a[2:4].
// (FIXED: previous round computed w^T @ va.)
// 32 warps; warp r handles rows r, r+32, ...; coalesced lane reads + shfl.
// Also resets g_maxbits.
// ---------------------------------------------------------------------------
__global__ __launch_bounds__(1024) void prep_kernel(const float* __restrict__ w,
                                                    const float* __restrict__ w_a,
                                                    const float* __restrict__ a) {
    __shared__ float va[256];
    const int tid = threadIdx.x;
    if (tid < 256) va[tid] = w_a[2 * tid] * a[2] + w_a[2 * tid + 1] * a[3];
    if (tid == 0) g_maxbits = 0u;
    __syncthreads();

    const int lane = tid & 31;
    const int warp = tid >> 5;
#pragma unroll
    for (int rr = 0; rr < 8; rr++) {
        const int r = warp + rr * 32;
        float s = 0.f;
#pragma unroll
        for (int t = 0; t < 8; t++) {
            const int o = t * 32 + lane;
            s += w[(size_t)r * 256 + o] * va[o];
        }
#pragma unroll
        for (int off = 16; off > 0; off >>= 1) s += __shfl_xor_sync(0xffffffffu, s, off);
        if (lane == 0) g_wv[r] = s;
    }
}

// ---------------------------------------------------------------------------
// Kernel 1: f_dst[i] = node[i,:] . wv ; global max via atomicMax on monotone
// key (order-independent => deterministic). f_src cancels in the row softmax.
// ---------------------------------------------------------------------------
__global__ __launch_bounds__(256) void fdst_kernel(const float* __restrict__ node) {
    __shared__ float wv[256];
    __shared__ float s_f[8];
    const int tid = threadIdx.x;
    wv[tid] = g_wv[tid];
    __syncthreads();

    const int lane = tid & 31;
    const int warp = tid >> 5;
    const int row = blockIdx.x * 8 + warp;
    const float* np = &node[(size_t)row * 256];

    float s = 0.f;
#pragma unroll
    for (int k = 0; k < 8; k++) {
        int c = lane + k * 32;
        s += np[c] * wv[c];
    }
#pragma unroll
    for (int o = 16; o > 0; o >>= 1) s += __shfl_xor_sync(0xffffffffu, s, o);
    if (lane == 0) { g_fdst[row] = s; s_f[warp] = s; }
    __syncthreads();
    if (tid == 0) {
        float m = s_f[0];
#pragma unroll
        for (int w = 1; w < 8; w++) m = fmaxf(m, s_f[w]);
        atomicMax(&g_maxbits, fkey(m));
    }
}

// ---------------------------------------------------------------------------
// Kernel 2: g_gv[i] = exp(f_dst[i] - M)
// ---------------------------------------------------------------------------
__global__ __launch_bounds__(1024) void gv_kernel() {
    const int row = blockIdx.x * 1024 + threadIdx.x;
    const float M = funkey(g_maxbits);
    g_gv[row] = __expf(g_fdst[row] - M);
}

// ---------------------------------------------------------------------------
// Kernel 3: fused GEMM + P:  P[i,:] = half( PSCALE * gv[i] * (node[i,:] @ w) )
// 128x64 tile, 256 threads, 8x4 microtile. grid = 4 x 64 = 256 CTAs.
// h_prime never touches memory.
// ---------------------------------------------------------------------------
__global__ __launch_bounds__(256) void gemm_kernel(const float* __restrict__ A,
                                                   const float* __restrict__ W) {
    __shared__ float As[16][128];
    __shared__ float Bs[16][64];

    const int m0 = blockIdx.y * 128;
    const int n0 = blockIdx.x * 64;
    const int tid = threadIdx.x;

    const int tr = tid >> 4;
    const int tc = tid & 15;
    const int ar = tid >> 1;
    const int ac = (tid & 1) * 8;
    const int br = tid >> 4;
    const int bc = (tid & 15) * 4;

    float acc[8][4];
#pragma unroll
    for (int i = 0; i < 8; i++)
#pragma unroll
        for (int j = 0; j < 4; j++) acc[i][j] = 0.f;

    for (int k0 = 0; k0 < 256; k0 += 16) {
        float4 a0 = *(const float4*)&A[(size_t)(m0 + ar) * 256 + k0 + ac];
        float4 a1 = *(const float4*)&A[(size_t)(m0 + ar) * 256 + k0 + ac + 4];
        float4 b0 = *(const float4*)&W[(size_t)(k0 + br) * 256 + n0 + bc];

        __syncthreads();
        As[ac + 0][ar] = a0.x; As[ac + 1][ar] = a0.y;
        As[ac + 2][ar] = a0.z; As[ac + 3][ar] = a0.w;
        As[ac + 4][ar] = a1.x; As[ac + 5][ar] = a1.y;
        As[ac + 6][ar] = a1.z; As[ac + 7][ar] = a1.w;
        *(float4*)&Bs[br][bc] = b0;
        __syncthreads();

#pragma unroll
        for (int k = 0; k < 16; k++) {
            float4 x0 = *(const float4*)&As[k][tr * 8];
            float4 x1 = *(const float4*)&As[k][tr * 8 + 4];
            float4 y0 = *(const float4*)&Bs[k][tc * 4];
            float ra[8] = {x0.x, x0.y, x0.z, x0.w, x1.x, x1.y, x1.z, x1.w};
            float rb[4] = {y0.x, y0.y, y0.z, y0.w};
#pragma unroll
            for (int i = 0; i < 8; i++)
#pragma unroll
                for (int j = 0; j < 4; j++) acc[i][j] += ra[i] * rb[j];
        }
    }

#pragma unroll
    for (int i = 0; i < 8; i++) {
        const int row = m0 + tr * 8 + i;
        const float gs = g_gv[row] * PSCALE;
        __half2 h01 = __floats2half2_rn(acc[i][0] * gs, acc[i][1] * gs);
        __half2 h23 = __floats2half2_rn(acc[i][2] * gs, acc[i][3] * gs);
        __half2* dst = (__half2*)&g_P[(size_t)row * 256 + n0 + tc * 4];
        dst[0] = h01;
        dst[1] = h23;
    }
}

// ---------------------------------------------------------------------------
// Kernel 4: per-row scan + aggregation + relu.
// out[i] = relu( (sum_{j in N(i)} P[j]) / (PSCALE * sum_{j in N(i)} gv[j]) )
// One CTA (256 thr) per row.
//  Phase A (coalesced): warp w owns cols [w*1024,(w+1)*1024); lane l iter k
//    loads arow4[w*256 + k*32 + l]; bit b=4k+c -> col = w*1024+(b>>2)*128+l*4+(b&3).
//    Fixed canonical extraction order -> deterministic.
//  Phase B: 4 groups x 64 threads; group g handles j==g (mod 4); each thread
//    loads half4 (uint2, 8B); fp32 accumulation; smem cross-group add.
// ---------------------------------------------------------------------------
__global__ __launch_bounds__(256) void attn_kernel(const float* __restrict__ Ahat,
                                                   float* __restrict__ out) {
    __shared__ int   s_flat[MAXT];      // 4 KB
    __shared__ float s_part[4 * 256];   // 4 KB
    __shared__ int   s_cnt[8];
    __shared__ float s_den[8];
    __shared__ int   s_off[9];

    const int tid = threadIdx.x;
    const int lane = tid & 31;
    const int wid = tid >> 5;
    const size_t row = blockIdx.x;

    // --- Phase A: coalesced presence-mask scan ---
    const float4* arow = (const float4*)(Ahat + row * NN);
    unsigned mask = 0u;
#pragma unroll
    for (int k = 0; k < 8; k++) {
        float4 v = __ldcs(&arow[wid * 256 + k * 32 + lane]);
        if (v.x > 0.f) mask |= 1u << (4 * k + 0);
        if (v.y > 0.f) mask |= 1u << (4 * k + 1);
        if (v.z > 0.f) mask |= 1u << (4 * k + 2);
        if (v.w > 0.f) mask |= 1u << (4 * k + 3);
    }
    int cnt = __popc(mask);

    int pre = cnt;
#pragma unroll
    for (int o = 1; o < 32; o <<= 1) {
        int n = __shfl_up_sync(0xffffffffu, pre, o);
        if (lane >= o) pre += n;
    }
    if (lane == 31) s_cnt[wid] = pre;
    __syncthreads();
    if (tid == 0) {
        int o = 0;
#pragma unroll
        for (int w = 0; w < 8; w++) { s_off[w] = o; o += s_cnt[w]; }
        s_off[8] = o;
    }
    __syncthreads();

    int off = s_off[wid] + (pre - cnt);
    float denl = 0.f;
    const int cbase = wid * 1024 + lane * 4;
    unsigned m = mask;
    while (m) {
        int b = __ffs(m) - 1;
        int col = cbase + (b >> 2) * 128 + (b & 3);
        if (off < MAXT) s_flat[off] = col;
        off++;
        denl += g_gv[col];
        m &= m - 1u;
    }

#pragma unroll
    for (int o = 16; o > 0; o >>= 1) denl += __shfl_xor_sync(0xffffffffu, denl, o);
    if (lane == 0) s_den[wid] = denl;
    __syncthreads();

    int nnz = s_off[8]; if (nnz > MAXT) nnz = MAXT;
    float den = ((s_den[0] + s_den[1]) + (s_den[2] + s_den[3])) +
                ((s_den[4] + s_den[5]) + (s_den[6] + s_den[7]));

    // --- Phase B: grouped half4 gather, fp32 accumulation ---
    const int g = tid >> 6;    // group 0..3
    const int c = tid & 63;    // half4 (uint2) index within row

    float ax = 0.f, ay = 0.f, az = 0.f, aw = 0.f;
    float bx = 0.f, by = 0.f, bz = 0.f, bw = 0.f;

    int j = g;
    for (; j + 4 < nnz; j += 8) {
        uint2 v0 = __ldg((const uint2*)&g_P[(size_t)s_flat[j + 0] * 256] + c);
        uint2 v1 = __ldg((const uint2*)&g_P[(size_t)s_flat[j + 4] * 256] + c);
        float2 l0 = __half22float2(*(const __half2*)&v0.x);
        float2 h0 = __half22float2(*(const __half2*)&v0.y);
        float2 l1 = __half22float2(*(const __half2*)&v1.x);
        float2 h1 = __half22float2(*(const __half2*)&v1.y);
        ax += l0.x; ay += l0.y; az += h0.x; aw += h0.y;
        bx += l1.x; by += l1.y; bz += h1.x; bw += h1.y;
    }
    for (; j < nnz; j += 4) {
        uint2 v0 = __ldg((const uint2*)&g_P[(size_t)s_flat[j] * 256] + c);
        float2 l0 = __half22float2(*(const __half2*)&v0.x);
        float2 h0 = __half22float2(*(const __half2*)&v0.y);
        ax += l0.x; ay += l0.y; az += h0.x; aw += h0.y;
    }
    ax += bx; ay += by; az += bz; aw += bw;

    *(float4*)&s_part[g * 256 + c * 4] = make_float4(ax, ay, az, aw);
    __syncthreads();

    const float invd = 1.f / (den * PSCALE);
    float r = ((s_part[0 * 256 + tid] + s_part[1 * 256 + tid]) +
               (s_part[2 * 256 + tid] + s_part[3 * 256 + tid]));
    out[row * 256 + tid] = fmaxf(r * invd, 0.f);
}

// ---------------------------------------------------------------------------
extern "C" void kernel_launch(void* const* d_in, const int* in_sizes, int n_in,
                              void* d_out, int out_size) {
    (void)in_sizes; (void)n_in; (void)out_size;
    const float* node = (const float*)d_in[0];
    const float* Ahat = (const float*)d_in[1];
    const float* w    = (const float*)d_in[2];
    const float* w_a  = (const float*)d_in[3];
    const float* a    = (const float*)d_in[4];
    float* out = (float*)d_out;

    prep_kernel<<<1, 1024>>>(w, w_a, a);
    fdst_kernel<<<NN / 8, 256>>>(node);
    gv_kernel<<<NN / 1024, 1024>>>();
    dim3 ggrid(4, 64);
    gemm_kernel<<<ggrid, 256>>>(node, w);
    attn_kernel<<<NN, 256>>>(Ahat, out);
}